// round 3
// baseline (speedup 1.0000x reference)
#include <cuda_runtime.h>
#include <cstdint>

#define BSZ    256
#define BOND   5
#define NDIM   128
#define ATOM   64
#define UNITS  128
#define THREADS 256

// smem float-word pitches (chosen for conflict-free mma fragment reads)
#define P_F    72    // F   [node=128][atom=64]   (72 % 32 == 8)
#define P_ADJ  132   // adj [m=128][n=128]        (132 % 32 == 4)
#define P_K    136   // K   [d=64][u=128]         (136 % 32 == 8)
#define P_X1   68    // X1  [m=128][d=64]         (68 % 32 == 4)

// smem layout in float words
#define OFF_F    0
#define OFF_ADJ  (OFF_F   + NDIM * P_F)     // 9216
#define OFF_K    (OFF_ADJ + NDIM * P_ADJ)   // 26112
#define OFF_X1   (OFF_K   + ATOM * P_K)     // 34816
#define SMEM_WORDS (OFF_X1 + NDIM * P_X1)   // 43520
#define SMEM_BYTES (SMEM_WORDS * 4)         // 174080

__device__ __forceinline__ uint32_t f2tf32(float f) {
    uint32_t u;
    asm("cvt.rna.tf32.f32 %0, %1;" : "=r"(u) : "f"(f));
    return u;
}
__device__ __forceinline__ float f2tf32f(float f) {
    return __uint_as_float(f2tf32(f));
}

__device__ __forceinline__ void mma_tf32(float c[4], const uint32_t a[4], const uint32_t b[2]) {
    asm volatile(
        "mma.sync.aligned.m16n8k8.row.col.f32.tf32.tf32.f32 "
        "{%0,%1,%2,%3}, {%4,%5,%6,%7}, {%8,%9}, {%0,%1,%2,%3};"
        : "+f"(c[0]), "+f"(c[1]), "+f"(c[2]), "+f"(c[3])
        : "r"(a[0]), "r"(a[1]), "r"(a[2]), "r"(a[3]), "r"(b[0]), "r"(b[1]));
}

__global__ void __launch_bounds__(THREADS, 1)
rgc_kernel(const float* __restrict__ adjacency,
           const float* __restrict__ features,
           const float* __restrict__ kern,
           float* __restrict__ out) {
    extern __shared__ float sm[];
    float* sF   = sm + OFF_F;
    float* sAdj = sm + OFF_ADJ;
    float* sK   = sm + OFF_K;
    float* sX1  = sm + OFF_X1;

    const int tid = threadIdx.x;
    const int wid = tid >> 5;
    const int lid = tid & 31;
    const int r4  = lid >> 2;   // groupID   (0..7)
    const int c4  = lid & 3;    // tid-in-group (0..3)
    const int b   = blockIdx.x;

    const int m0  = (wid & 3) * 32;        // M tile base (both GEMMs)
    const int nd0 = (wid >> 2) * 32;       // GEMM1 N (=atom d) tile base
    const int u0  = (wid >> 2) * 64;       // GEMM2 N (=units) tile base

    const float4* adj4  = reinterpret_cast<const float4*>(adjacency);
    const float4* ker4  = reinterpret_cast<const float4*>(kern);
    const float4* feat4 = reinterpret_cast<const float4*>(features);

    // ---- stage F once: F[node][atom], pitch 72 ----
    {
        const float4* src = feat4 + (size_t)b * 2048;   // 128 rows x 16 float4
        #pragma unroll
        for (int t = 0; t < 8; t++) {
            int i = tid + t * THREADS;                  // 0..2047
            float4 v = src[i];
            int node = i >> 4, a4 = i & 15;
            float* d = sF + node * P_F + a4 * 4;
            d[0] = f2tf32f(v.x); d[1] = f2tf32f(v.y);
            d[2] = f2tf32f(v.z); d[3] = f2tf32f(v.w);
        }
    }

    // GEMM2 accumulator: OUT tile 32(m) x 64(u) per warp, persists across bonds
    float acc2[2][8][4];
    #pragma unroll
    for (int mt = 0; mt < 2; mt++)
        #pragma unroll
        for (int nt = 0; nt < 8; nt++)
            #pragma unroll
            for (int k = 0; k < 4; k++) acc2[mt][nt][k] = 0.0f;

    for (int e = 0; e < BOND; e++) {
        if (e > 0) __syncthreads();   // prev GEMM2 done before overwriting adj/K/X1

        // ---- stage adjacency A_e[m=128][n=128], pitch 132 ----
        {
            const float4* src = adj4 + (size_t)(b * BOND + e) * 4096;
            #pragma unroll
            for (int t = 0; t < 16; t++) {
                int i = tid + t * THREADS;              // 0..4095
                float4 v = src[i];
                int m = i >> 5, n4 = i & 31;
                float* d = sAdj + m * P_ADJ + n4 * 4;
                d[0] = f2tf32f(v.x); d[1] = f2tf32f(v.y);
                d[2] = f2tf32f(v.z); d[3] = f2tf32f(v.w);
            }
        }
        // ---- stage K_e[d=64][u=128], pitch 136 ----
        {
            const float4* src = ker4 + (size_t)(b * BOND + e) * 2048;
            #pragma unroll
            for (int t = 0; t < 8; t++) {
                int i = tid + t * THREADS;              // 0..2047
                float4 v = src[i];
                int dd = i >> 5, u4 = i & 31;
                float* d = sK + dd * P_K + u4 * 4;
                d[0] = f2tf32f(v.x); d[1] = f2tf32f(v.y);
                d[2] = f2tf32f(v.z); d[3] = f2tf32f(v.w);
            }
        }
        __syncthreads();

        // ---- GEMM1: X1[m,d] = sum_n adj[m,n] * F[n,d]; warp tile 32x32 ----
        float acc1[2][4][4];
        #pragma unroll
        for (int mt = 0; mt < 2; mt++)
            #pragma unroll
            for (int nt = 0; nt < 4; nt++)
                #pragma unroll
                for (int k = 0; k < 4; k++) acc1[mt][nt][k] = 0.0f;

        #pragma unroll 4
        for (int ks = 0; ks < 16; ks++) {
            const int k0 = ks * 8;
            uint32_t a[2][4];
            #pragma unroll
            for (int mt = 0; mt < 2; mt++) {
                const int row = m0 + mt * 16 + r4;
                const float* pa = sAdj + row * P_ADJ + k0 + c4;
                a[mt][0] = __float_as_uint(pa[0]);
                a[mt][1] = __float_as_uint(pa[8 * P_ADJ]);
                a[mt][2] = __float_as_uint(pa[4]);
                a[mt][3] = __float_as_uint(pa[8 * P_ADJ + 4]);
            }
            uint32_t bf[4][2];
            #pragma unroll
            for (int nt = 0; nt < 4; nt++) {
                const int nn = nd0 + nt * 8 + r4;
                const float* pb = sF + (k0 + c4) * P_F + nn;
                bf[nt][0] = __float_as_uint(pb[0]);
                bf[nt][1] = __float_as_uint(pb[4 * P_F]);
            }
            #pragma unroll
            for (int mt = 0; mt < 2; mt++)
                #pragma unroll
                for (int nt = 0; nt < 4; nt++)
                    mma_tf32(acc1[mt][nt], a[mt], bf[nt]);
        }

        // ---- X1 -> smem (re-rounded to tf32: it is the A operand of GEMM2) ----
        #pragma unroll
        for (int mt = 0; mt < 2; mt++) {
            #pragma unroll
            for (int nt = 0; nt < 4; nt++) {
                const int row = m0 + mt * 16 + r4;
                const int col = nd0 + nt * 8 + 2 * c4;
                float2* p0 = reinterpret_cast<float2*>(sX1 + row * P_X1 + col);
                float2* p1 = reinterpret_cast<float2*>(sX1 + (row + 8) * P_X1 + col);
                *p0 = make_float2(f2tf32f(acc1[mt][nt][0]), f2tf32f(acc1[mt][nt][1]));
                *p1 = make_float2(f2tf32f(acc1[mt][nt][2]), f2tf32f(acc1[mt][nt][3]));
            }
        }
        __syncthreads();

        // ---- GEMM2: OUT[m,u] += sum_d X1[m,d] * K[d,u]; warp tile 32x64 ----
        #pragma unroll 2
        for (int ks = 0; ks < 8; ks++) {
            const int k0 = ks * 8;
            uint32_t a[2][4];
            #pragma unroll
            for (int mt = 0; mt < 2; mt++) {
                const int row = m0 + mt * 16 + r4;
                const float* pa = sX1 + row * P_X1 + k0 + c4;
                a[mt][0] = __float_as_uint(pa[0]);
                a[mt][1] = __float_as_uint(pa[8 * P_X1]);
                a[mt][2] = __float_as_uint(pa[4]);
                a[mt][3] = __float_as_uint(pa[8 * P_X1 + 4]);
            }
            uint32_t bf[8][2];
            #pragma unroll
            for (int nt = 0; nt < 8; nt++) {
                const int nn = u0 + nt * 8 + r4;
                const float* pb = sK + (k0 + c4) * P_K + nn;
                bf[nt][0] = __float_as_uint(pb[0]);
                bf[nt][1] = __float_as_uint(pb[4 * P_K]);
            }
            #pragma unroll
            for (int mt = 0; mt < 2; mt++)
                #pragma unroll
                for (int nt = 0; nt < 8; nt++)
                    mma_tf32(acc2[mt][nt], a[mt], bf[nt]);
        }
    }

    // ---- epilogue: ReLU + store OUT[b][m][u] ----
    float* ob = out + (size_t)b * (NDIM * UNITS);
    #pragma unroll
    for (int mt = 0; mt < 2; mt++) {
        #pragma unroll
        for (int nt = 0; nt < 8; nt++) {
            const int row = m0 + mt * 16 + r4;
            const int col = u0 + nt * 8 + 2 * c4;
            float2 v0 = make_float2(fmaxf(acc2[mt][nt][0], 0.0f), fmaxf(acc2[mt][nt][1], 0.0f));
            float2 v1 = make_float2(fmaxf(acc2[mt][nt][2], 0.0f), fmaxf(acc2[mt][nt][3], 0.0f));
            *reinterpret_cast<float2*>(ob + row * UNITS + col)       = v0;
            *reinterpret_cast<float2*>(ob + (row + 8) * UNITS + col) = v1;
        }
    }
}

extern "C" void kernel_launch(void* const* d_in, const int* in_sizes, int n_in,
                              void* d_out, int out_size) {
    const float* adj  = nullptr;
    const float* feat = nullptr;
    const float* ker  = nullptr;
    for (int i = 0; i < n_in; i++) {
        if      (in_sizes[i] == BSZ * BOND * NDIM * NDIM)  adj  = (const float*)d_in[i];
        else if (in_sizes[i] == BSZ * NDIM * ATOM)         feat = (const float*)d_in[i];
        else if (in_sizes[i] == BSZ * BOND * ATOM * UNITS) ker  = (const float*)d_in[i];
    }
    if (!adj)  adj  = (const float*)d_in[0];
    if (!feat) feat = (const float*)d_in[1];
    if (!ker)  ker  = (const float*)d_in[2];

    static bool attr_set = false;
    if (!attr_set) {
        cudaFuncSetAttribute(rgc_kernel, cudaFuncAttributeMaxDynamicSharedMemorySize, SMEM_BYTES);
        attr_set = true;
    }
    rgc_kernel<<<BSZ, THREADS, SMEM_BYTES>>>(adj, feat, ker, (float*)d_out);
}